// round 4
// baseline (speedup 1.0000x reference)
#include <cuda_runtime.h>

// HOAF: per-group (G=32, cpg=8) polynomial expansion (164 features) +
// per-group 8x164 matvec. B=16, C=256, HW=3136.
//
// R3: R2 was co-bound (fma 54%, L1 53%) with occ 20%. Now 4 pixel-units per
// thread (batches b, b+4, b+8, b+12 at the same pixel pair) and the 8 outputs
// split into two passes of 4 -> 2 LDS.128 per feature feed 16 FFMA2
// (2B/FFMA2, half of R2) while acc regs stay at 32. Deg2/3 muls are
// recomputed per pass (+10.6% fma work). Predicted fma ~80%, ~75us.

typedef unsigned long long u64;

#define HW   3136
#define TPB  224

__device__ __forceinline__ u64 fma2(u64 a, u64 b, u64 c) {
    u64 d;
    asm("fma.rn.f32x2 %0, %1, %2, %3;" : "=l"(d) : "l"(a), "l"(b), "l"(c));
    return d;
}
__device__ __forceinline__ u64 mul2(u64 a, u64 b) {
    u64 d;
    asm("mul.rn.f32x2 %0, %1, %2;" : "=l"(d) : "l"(a), "l"(b), "l"(b));
    return d;
}

__global__ __launch_bounds__(TPB, 2) void hoaf_kernel(
    const float* __restrict__ x,
    const float* __restrict__ w1, const float* __restrict__ b1,
    const float* __restrict__ w2, const float* __restrict__ b2,
    const float* __restrict__ w3, const float* __restrict__ b3,
    float* __restrict__ out)
{
    // [half][feature][output-in-half], each entry (w,w) packed
    __shared__ alignas(16) u64 wdup[2][164][4];
    __shared__ u64 biasdup[2][4];

    const int tid = threadIdx.x;
    const int g = blockIdx.y;

    // Stage this group's weights, duplicated into both f32x2 lanes.
    // Feature f: [0,8)=deg1, [8,44)=deg2 (triu), [44,164)=deg3 (sorted
    // triples) -- identical ordering to the reference.
    for (int idx = tid; idx < 1312; idx += TPB) {
        const int f = idx >> 3;
        const int o = idx & 7;
        float v;
        if (f < 8)        v = w1[(g * 8 + o) * 8   + f];
        else if (f < 44)  v = w2[(g * 8 + o) * 36  + (f - 8)];
        else              v = w3[(g * 8 + o) * 120 + (f - 44)];
        const unsigned int u = __float_as_uint(v);
        wdup[o >> 2][f][o & 3] = ((u64)u << 32) | u;
    }
    if (tid < 8) {
        const float v = b1[g * 8 + tid] + b2[g * 8 + tid] + b3[g * 8 + tid];
        const unsigned int u = __float_as_uint(v);
        biasdup[tid >> 2][tid & 3] = ((u64)u << 32) | u;
    }
    __syncthreads();

    // Pixel pair p in batches z, z+4, z+8, z+12.
    const int p = (blockIdx.x * TPB + tid) * 2;
    const size_t gbase = ((size_t)blockIdx.z * 256 + (size_t)g * 8) * HW + p;
    const size_t bstr  = (size_t)4 * 256 * HW;

    u64 X[4][8];
#pragma unroll
    for (int u = 0; u < 4; u++)
#pragma unroll
        for (int k = 0; k < 8; k++)
            X[u][k] = *(const u64*)(x + gbase + u * bstr + (size_t)k * HW);

#pragma unroll
    for (int pass = 0; pass < 2; pass++) {
        u64 acc[4][4];
#pragma unroll
        for (int u = 0; u < 4; u++)
#pragma unroll
            for (int o = 0; o < 4; o++)
                acc[u][o] = biasdup[pass][o];

        // One feature (4 units) into 4 outputs: 2 LDS.128, 16 FFMA2.
        auto accF = [&](int f, u64 f0, u64 f1, u64 f2, u64 f3) {
            const ulonglong2* wp = (const ulonglong2*)wdup[pass][f];
            const ulonglong2 wa = wp[0], wb = wp[1];
            acc[0][0] = fma2(f0, wa.x, acc[0][0]);
            acc[1][0] = fma2(f1, wa.x, acc[1][0]);
            acc[2][0] = fma2(f2, wa.x, acc[2][0]);
            acc[3][0] = fma2(f3, wa.x, acc[3][0]);
            acc[0][1] = fma2(f0, wa.y, acc[0][1]);
            acc[1][1] = fma2(f1, wa.y, acc[1][1]);
            acc[2][1] = fma2(f2, wa.y, acc[2][1]);
            acc[3][1] = fma2(f3, wa.y, acc[3][1]);
            acc[0][2] = fma2(f0, wb.x, acc[0][2]);
            acc[1][2] = fma2(f1, wb.x, acc[1][2]);
            acc[2][2] = fma2(f2, wb.x, acc[2][2]);
            acc[3][2] = fma2(f3, wb.x, acc[3][2]);
            acc[0][3] = fma2(f0, wb.y, acc[0][3]);
            acc[1][3] = fma2(f1, wb.y, acc[1][3]);
            acc[2][3] = fma2(f2, wb.y, acc[2][3]);
            acc[3][3] = fma2(f3, wb.y, acc[3][3]);
        };

        // Degree 1
#pragma unroll
        for (int k = 0; k < 8; k++)
            accF(k, X[0][k], X[1][k], X[2][k], X[3][k]);

        // Degree 2 + 3 fused; pair products reused for triples.
        int f2 = 8, f3 = 44;
#pragma unroll
        for (int i = 0; i < 8; i++) {
#pragma unroll
            for (int j = i; j < 8; j++) {
                const u64 p0 = mul2(X[0][i], X[0][j]);
                const u64 p1 = mul2(X[1][i], X[1][j]);
                const u64 p2 = mul2(X[2][i], X[2][j]);
                const u64 p3 = mul2(X[3][i], X[3][j]);
                accF(f2, p0, p1, p2, p3);
                f2++;
#pragma unroll
                for (int k = j; k < 8; k++) {
                    accF(f3, mul2(p0, X[0][k]), mul2(p1, X[1][k]),
                             mul2(p2, X[2][k]), mul2(p3, X[3][k]));
                    f3++;
                }
            }
        }

        // Store this half's 4 outputs for all 4 units.
#pragma unroll
        for (int u = 0; u < 4; u++)
#pragma unroll
            for (int o = 0; o < 4; o++)
                *(u64*)(out + gbase + u * bstr + (size_t)(pass * 4 + o) * HW)
                    = acc[u][o];
    }
}

extern "C" void kernel_launch(void* const* d_in, const int* in_sizes, int n_in,
                              void* d_out, int out_size)
{
    const float* x  = (const float*)d_in[0];
    const float* w1 = (const float*)d_in[1];
    const float* b1 = (const float*)d_in[2];
    const float* w2 = (const float*)d_in[3];
    const float* b2 = (const float*)d_in[4];
    const float* w3 = (const float*)d_in[5];
    const float* b3 = (const float*)d_in[6];

    dim3 grid(7, 32, 4);    // pixel-pair chunks, groups, batch quartets
    dim3 block(TPB);
    hoaf_kernel<<<grid, block>>>(x, w1, b1, w2, b2, w3, b3, (float*)d_out);
}